// round 7
// baseline (speedup 1.0000x reference)
#include <cuda_runtime.h>
#include <cuda_bf16.h>
#include <math.h>
#include <stdint.h>

#define Nn 10000
#define Ee 160000
#define Aa 8
#define D1C 512
#define EMBC 128
#define ATTRC 64
#define NFC 1500
#define NRC 64
#define NBM 16
#define NBF 64

// ---------------- device scratch ----------------
__device__ __align__(16) float g_xl1[Nn * D1C];
__device__ __align__(16) float g_xr1[Nn * D1C];
__device__ __align__(16) float g_h[Nn * D1C];
__device__ __align__(16) float g_xl2[Nn * D1C];
__device__ __align__(16) float g_xr2[Nn * D1C];
__device__ __align__(16) float g_hbuf2[Aa * Nn * D1C];
__device__ __align__(16) float g_eproj1[ATTRC * D1C];
__device__ __align__(16) float g_eproj2[ATTRC * D1C];
__device__ __align__(16) float g_meanproj1[D1C];
__device__ __align__(16) float g_meanproj2[Aa * D1C];
__device__ int   g_deg[Nn];
__device__ int   g_offs[Nn + 1];
__device__ int   g_cursor[Nn];
__device__ int   g_esrc[Ee];
__device__ int   g_eattr[Ee];
__device__ unsigned g_mask0[Nn];
__device__ unsigned g_mask1[Nn];
__device__ int   g_histF[ATTRC];
__device__ int   g_histM[Aa * ATTRC];
__device__ int   g_pairofs[Aa + 1];
__device__ int   g_pair[Aa * Nn];
__device__ float g_partM[Aa * NBM * 3 * D1C];
__device__ float g_partF[NBF * 3 * D1C];
__device__ __align__(16) __nv_bfloat16 g_Bh1[1024 * EMBC];
__device__ __align__(16) __nv_bfloat16 g_Bl1[1024 * EMBC];
__device__ __align__(16) __nv_bfloat16 g_Bh2[1024 * D1C];
__device__ __align__(16) __nv_bfloat16 g_Bl2[1024 * D1C];

// ---------------- mma.sync helpers ----------------
__device__ __forceinline__ uint32_t smem_u32(const void* p) {
    uint32_t a;
    asm("{ .reg .u64 t; cvta.to.shared.u64 t, %1; cvt.u32.u64 %0, t; }" : "=r"(a) : "l"(p));
    return a;
}
__device__ __forceinline__ void ldsm4(uint32_t& r0, uint32_t& r1, uint32_t& r2, uint32_t& r3, uint32_t addr) {
    asm volatile("ldmatrix.sync.aligned.m8n8.x4.shared.b16 {%0,%1,%2,%3}, [%4];"
                 : "=r"(r0), "=r"(r1), "=r"(r2), "=r"(r3) : "r"(addr));
}
__device__ __forceinline__ void mma16816(float* c, const uint32_t* a, const uint32_t* b) {
    asm volatile("mma.sync.aligned.m16n8k16.row.col.f32.bf16.bf16.f32 "
                 "{%0,%1,%2,%3}, {%4,%5,%6,%7}, {%8,%9}, {%0,%1,%2,%3};"
                 : "+f"(c[0]), "+f"(c[1]), "+f"(c[2]), "+f"(c[3])
                 : "r"(a[0]), "r"(a[1]), "r"(a[2]), "r"(a[3]), "r"(b[0]), "r"(b[1]));
}

// ---------------- prep kernels ----------------
__global__ void zeroK_kernel() {
    int i = blockIdx.x * 512 + threadIdx.x;
    if (i < Nn) { g_deg[i] = 0; g_mask0[i] = 0u; }
    if (i < ATTRC) g_histF[i] = 0;
    if (i < Aa * ATTRC) g_histM[i] = 0;
}

__global__ void wsplit1_kernel(const float* __restrict__ Wl1, const float* __restrict__ Wr1) {
    int idx = blockIdx.x * 512 + threadIdx.x;
    int n = idx >> 7, k = idx & 127;
    const float* W = (n < 512) ? Wl1 : Wr1;
    float v = W[(size_t)k * 512 + (n & 511)];
    __nv_bfloat16 h = __float2bfloat16(v);
    g_Bh1[idx] = h;
    g_Bl1[idx] = __float2bfloat16(v - __bfloat162float(h));
}

__global__ void wsplit2_kernel(const float* __restrict__ Wl2, const float* __restrict__ Wr2) {
    int idx = blockIdx.x * 512 + threadIdx.x;
    int n = idx >> 9, k = idx & 511;
    const float* W = (n < 512) ? Wl2 : Wr2;
    float v = W[(size_t)k * 512 + (n & 511)];
    __nv_bfloat16 h = __float2bfloat16(v);
    g_Bh2[idx] = h;
    g_Bl2[idx] = __float2bfloat16(v - __bfloat162float(h));
}

__global__ void eproj_kernel(const float* __restrict__ pe,
                             const float* __restrict__ We1,
                             const float* __restrict__ We2) {
    int a = blockIdx.x, c = threadIdx.x;
    __shared__ float row[EMBC];
    if (c < EMBC) row[c] = pe[a * EMBC + c];
    __syncthreads();
    float s1 = 0.f, s2 = 0.f;
#pragma unroll 8
    for (int k = 0; k < EMBC; k++) {
        float p = row[k];
        s1 += p * We1[k * D1C + c];
        s2 += p * We2[k * D1C + c];
    }
    g_eproj1[a * D1C + c] = s1;
    g_eproj2[a * D1C + c] = s2;
}

__global__ void degK_kernel(const int* __restrict__ ei) {
    int e = blockIdx.x * 256 + threadIdx.x;
    if (e < Ee) atomicAdd(&g_deg[ei[Ee + e]], 1);
}

__global__ void seedK_kernel(const int* __restrict__ args) {
    if (threadIdx.x < Aa) atomicOr(&g_mask0[args[threadIdx.x]], 1u << threadIdx.x);
}

__global__ void copy_mask_kernel(int dir) {
    int i = blockIdx.x * 512 + threadIdx.x;
    if (i < Nn) {
        if (dir == 0) g_mask1[i] = g_mask0[i];
        else          g_mask0[i] = g_mask1[i];
    }
}

__global__ void hop_kernel(const int* __restrict__ ei, int dir) {
    int e = blockIdx.x * blockDim.x + threadIdx.x;
    if (e >= Ee) return;
    int s = ei[e], d = ei[Ee + e];
    const unsigned* cur = dir == 0 ? g_mask0 : g_mask1;
    unsigned* nxt = dir == 0 ? g_mask1 : g_mask0;
    unsigned m = cur[d];
    if (m) atomicOr(&nxt[s], m);
}

__global__ void histF_kernel(const int* __restrict__ attr) {
    __shared__ int shF[ATTRC];
    int t = threadIdx.x;
    if (t < ATTRC) shF[t] = 0;
    __syncthreads();
    for (int e = blockIdx.x * blockDim.x + t; e < Ee; e += gridDim.x * blockDim.x)
        atomicAdd(&shF[attr[e]], 1);
    __syncthreads();
    if (t < ATTRC && shF[t]) atomicAdd(&g_histF[t], shF[t]);
}

__global__ void histM_kernel(const int* __restrict__ ei, const int* __restrict__ attr) {
    __shared__ int shM[Aa * ATTRC];
    int t = threadIdx.x;
    for (int i = t; i < Aa * ATTRC; i += blockDim.x) shM[i] = 0;
    __syncthreads();
    for (int e = blockIdx.x * blockDim.x + t; e < Ee; e += gridDim.x * blockDim.x) {
        int a = attr[e];
        unsigned mb = g_mask1[ei[e]] & g_mask1[ei[Ee + e]];
        while (mb) {
            int i = __ffs(mb) - 1;
            mb &= mb - 1;
            atomicAdd(&shM[i * ATTRC + a], 1);
        }
    }
    __syncthreads();
    for (int i = t; i < Aa * ATTRC; i += blockDim.x) if (shM[i]) atomicAdd(&g_histM[i], shM[i]);
}

__global__ void meanprojF_kernel() {
    int c = threadIdx.x;
    float s = 0.f, tot = 0.f;
    for (int a = 0; a < ATTRC; a++) {
        float hh = (float)g_histF[a];
        tot += hh;
        s += hh * g_eproj1[a * D1C + c];
    }
    g_meanproj1[c] = s / fmaxf(tot, 1.f);
}

__global__ void meanprojM_kernel() {
    int i = blockIdx.x, c = threadIdx.x;
    float s = 0.f, tot = 0.f;
    for (int a = 0; a < ATTRC; a++) {
        float hh = (float)g_histM[i * ATTRC + a];
        tot += hh;
        s += hh * g_eproj2[a * D1C + c];
    }
    g_meanproj2[i * D1C + c] = s / fmaxf(tot, 1.f);
}

// ---------------- pair compaction (deterministic, node-ordered) ----------------
__global__ void pairscan_kernel() {
    __shared__ unsigned long long shA[1024], shB[1024];
    int t = threadIdx.x;
    int base = t * 10;
    unsigned mloc[10];
    unsigned long long a = 0, bv = 0;
#pragma unroll
    for (int i = 0; i < 10; i++) {
        int idx = base + i;
        unsigned mm = (idx < Nn) ? g_mask1[idx] : 0u;
        mloc[i] = mm;
#pragma unroll
        for (int b = 0; b < 4; b++) a += (unsigned long long)((mm >> b) & 1u) << (16 * b);
#pragma unroll
        for (int b = 0; b < 4; b++) bv += (unsigned long long)((mm >> (b + 4)) & 1u) << (16 * b);
    }
    shA[t] = a; shB[t] = bv;
    __syncthreads();
    for (int off = 1; off < 1024; off <<= 1) {
        unsigned long long va = (t >= off) ? shA[t - off] : 0ULL;
        unsigned long long vb = (t >= off) ? shB[t - off] : 0ULL;
        __syncthreads();
        shA[t] += va; shB[t] += vb;
        __syncthreads();
    }
    unsigned long long totA = shA[1023], totB = shB[1023];
    int ofs[Aa + 1];
    ofs[0] = 0;
#pragma unroll
    for (int b = 0; b < 4; b++) ofs[b + 1] = ofs[b] + (int)((totA >> (16 * b)) & 0xFFFF);
#pragma unroll
    for (int b = 4; b < 8; b++) ofs[b + 1] = ofs[b] + (int)((totB >> (16 * (b - 4))) & 0xFFFF);
    if (t == 0)
        for (int b = 0; b <= Aa; b++) g_pairofs[b] = ofs[b];
    unsigned long long exA = shA[t] - a, exB = shB[t] - bv;
    int cur[8];
#pragma unroll
    for (int b = 0; b < 4; b++) cur[b] = ofs[b] + (int)((exA >> (16 * b)) & 0xFFFF);
#pragma unroll
    for (int b = 4; b < 8; b++) cur[b] = ofs[b] + (int)((exB >> (16 * (b - 4))) & 0xFFFF);
#pragma unroll
    for (int i = 0; i < 10; i++) {
        int idx = base + i;
        if (idx < Nn) {
            unsigned mm = mloc[i];
            while (mm) {
                int b = __ffs(mm) - 1;
                mm &= mm - 1;
                g_pair[cur[b]++] = idx | (b << 20);
            }
        }
    }
}

// ---------------- HMMA GEMM ----------------
#define GSTRIDE 72
#define GTILE_BYTES (128 * GSTRIDE * 2)
#define GDYN (4 * GTILE_BYTES)

__global__ void __launch_bounds__(256, 1)
mma_gemm_kernel(const float* __restrict__ A, const int* __restrict__ gidx,
                const __nv_bfloat16* __restrict__ Bh, const __nv_bfloat16* __restrict__ Bl,
                float* __restrict__ Cl, float* __restrict__ Cr, int K) {
    extern __shared__ char dyn[];
    char* pAh = dyn;
    char* pAl = dyn + GTILE_BYTES;
    char* pBh = dyn + 2 * GTILE_BYTES;
    char* pBl = dyn + 3 * GTILE_BYTES;
    uint32_t sAh = smem_u32(pAh), sAl = smem_u32(pAl);
    uint32_t sBh = smem_u32(pBh), sBl = smem_u32(pBl);

    const int tid = threadIdx.x, wid = tid >> 5, lane = tid & 31;
    const int warp_m = wid & 1, warp_n = wid >> 1;
    const int row0 = blockIdx.x * 128;
    const int coltile = blockIdx.y;

    float acc[4][4][4];
#pragma unroll
    for (int mi = 0; mi < 4; mi++)
#pragma unroll
        for (int ni = 0; ni < 4; ni++)
#pragma unroll
            for (int q = 0; q < 4; q++) acc[mi][ni][q] = 0.f;

    const int lane15 = lane & 15, khalfA = lane >> 4;
    const int nrow = (lane & 7) | ((lane >> 4) << 3), khB = (lane >> 3) & 1;

    const int nch = K >> 6;
    for (int ch = 0; ch < nch; ch++) {
#pragma unroll
        for (int it = 0; it < 8; it++) {
            int i = tid + it * 256;
            int r = i >> 4, k4 = i & 15;
            int row = row0 + r;
            float4 v = make_float4(0.f, 0.f, 0.f, 0.f);
            if (row < Nn) {
                int ar = gidx ? gidx[row] : row;
                v = *(const float4*)(A + (size_t)ar * K + (ch << 6) + (k4 << 2));
            }
            __nv_bfloat16 h0 = __float2bfloat16(v.x), h1 = __float2bfloat16(v.y);
            __nv_bfloat16 h2 = __float2bfloat16(v.z), h3 = __float2bfloat16(v.w);
            __nv_bfloat16 l0 = __float2bfloat16(v.x - __bfloat162float(h0));
            __nv_bfloat16 l1 = __float2bfloat16(v.y - __bfloat162float(h1));
            __nv_bfloat16 l2 = __float2bfloat16(v.z - __bfloat162float(h2));
            __nv_bfloat16 l3 = __float2bfloat16(v.w - __bfloat162float(h3));
            uint32_t off = r * (GSTRIDE * 2) + k4 * 8;
            __nv_bfloat162 hA = __halves2bfloat162(h0, h1), hB = __halves2bfloat162(h2, h3);
            __nv_bfloat162 lA = __halves2bfloat162(l0, l1), lB = __halves2bfloat162(l2, l3);
            *(uint2*)(pAh + off) = make_uint2(*(uint32_t*)&hA, *(uint32_t*)&hB);
            *(uint2*)(pAl + off) = make_uint2(*(uint32_t*)&lA, *(uint32_t*)&lB);
        }
#pragma unroll
        for (int it = 0; it < 4; it++) {
            int i = tid + it * 256;
            int n = i >> 3, k8 = i & 7;
            size_t gofs = (size_t)(coltile * 128 + n) * K + (ch << 6) + (k8 << 3);
            uint4 hv = *(const uint4*)(Bh + gofs);
            uint4 lv = *(const uint4*)(Bl + gofs);
            uint32_t off = n * (GSTRIDE * 2) + k8 * 16;
            *(uint4*)(pBh + off) = hv;
            *(uint4*)(pBl + off) = lv;
        }
        __syncthreads();

#pragma unroll
        for (int ks = 0; ks < 4; ks++) {
            int k0 = ks * 16;
            uint32_t ah[4][4], al[4][4], bh[2][4], bl[2][4];
#pragma unroll
            for (int mi = 0; mi < 4; mi++) {
                uint32_t ro = (warp_m * 64 + mi * 16 + lane15) * (GSTRIDE * 2) + k0 * 2 + khalfA * 16;
                ldsm4(ah[mi][0], ah[mi][1], ah[mi][2], ah[mi][3], sAh + ro);
                ldsm4(al[mi][0], al[mi][1], al[mi][2], al[mi][3], sAl + ro);
            }
#pragma unroll
            for (int pr = 0; pr < 2; pr++) {
                uint32_t ro = (warp_n * 32 + pr * 16 + nrow) * (GSTRIDE * 2) + k0 * 2 + khB * 16;
                ldsm4(bh[pr][0], bh[pr][1], bh[pr][2], bh[pr][3], sBh + ro);
                ldsm4(bl[pr][0], bl[pr][1], bl[pr][2], bl[pr][3], sBl + ro);
            }
#pragma unroll
            for (int mi = 0; mi < 4; mi++)
#pragma unroll
                for (int ni = 0; ni < 4; ni++) {
                    int pr = ni >> 1, ix = (ni & 1) * 2;
                    uint32_t bhv[2] = {bh[pr][ix], bh[pr][ix + 1]};
                    uint32_t blv[2] = {bl[pr][ix], bl[pr][ix + 1]};
                    mma16816(acc[mi][ni], ah[mi], bhv);
                    mma16816(acc[mi][ni], ah[mi], blv);
                    mma16816(acc[mi][ni], al[mi], bhv);
                }
        }
        __syncthreads();
    }

    float* dstbase;
    int colbase;
    if (coltile < 4) { dstbase = Cl; colbase = coltile * 128; }
    else             { dstbase = Cr; colbase = (coltile - 4) * 128; }
    colbase += warp_n * 32;
#pragma unroll
    for (int mi = 0; mi < 4; mi++) {
        int r0r = row0 + warp_m * 64 + mi * 16 + (lane >> 2);
#pragma unroll
        for (int ni = 0; ni < 4; ni++) {
            int cc = colbase + ni * 8 + (lane & 3) * 2;
            if (r0r < Nn)
                *(float2*)(dstbase + (size_t)r0r * 512 + cc) = make_float2(acc[mi][ni][0], acc[mi][ni][1]);
            if (r0r + 8 < Nn)
                *(float2*)(dstbase + (size_t)(r0r + 8) * 512 + cc) = make_float2(acc[mi][ni][2], acc[mi][ni][3]);
        }
    }
}

// ---------------- CSR scan/fill ----------------
__global__ void scan_kernel() {
    __shared__ int sh[1024];
    int t = threadIdx.x;
    int base = t * 10;
    int loc[10];
    int s = 0;
#pragma unroll
    for (int i = 0; i < 10; i++) {
        int idx = base + i;
        loc[i] = (idx < Nn) ? g_deg[idx] : 0;
        s += loc[i];
    }
    sh[t] = s;
    __syncthreads();
    for (int off = 1; off < 1024; off <<= 1) {
        int v = (t >= off) ? sh[t - off] : 0;
        __syncthreads();
        sh[t] += v;
        __syncthreads();
    }
    int run = (t > 0) ? sh[t - 1] : 0;
#pragma unroll
    for (int i = 0; i < 10; i++) {
        int idx = base + i;
        if (idx < Nn) {
            g_offs[idx] = run;
            g_cursor[idx] = run;
            run += loc[i];
        }
    }
    if (t == 0) g_offs[Nn] = Ee;
}

__global__ void fill_kernel(const int* __restrict__ ei, const int* __restrict__ attr) {
    int e = blockIdx.x * blockDim.x + threadIdx.x;
    if (e >= Ee) return;
    int d = ei[Ee + e];
    int pos = atomicAdd(&g_cursor[d], 1);
    g_esrc[pos] = ei[e];
    g_eattr[pos] = attr[e];
}

// ---------------- GAT layer-1 ----------------
__global__ void gat1_kernel(const float* __restrict__ xl, const float* __restrict__ xr,
                            const float* __restrict__ eproj, const float* __restrict__ meanproj,
                            const float* __restrict__ att, const float* __restrict__ bias,
                            float* __restrict__ out) {
    int warp = threadIdx.x >> 5;
    int lane = threadIdx.x & 31;
    int dst = blockIdx.x * 8 + warp;
    if (dst >= Nn) return;

    float attreg[16], xrreg[16], acc[16];
    float m[4], r[4];
#pragma unroll
    for (int j = 0; j < 16; j++) {
        attreg[j] = att[(j >> 2) * 128 + lane + 32 * (j & 3)];
        xrreg[j] = xr[(size_t)dst * D1C + lane + 32 * j];
        acc[j] = 0.f;
    }
#pragma unroll
    for (int h = 0; h < 4; h++) { m[h] = -INFINITY; r[h] = 0.f; }

    int beg = g_offs[dst], end = g_offs[dst + 1];
    for (int k = beg; k <= end; k++) {
        int src;
        const float* eerow;
        if (k < end) {
            src = g_esrc[k];
            eerow = eproj + (size_t)g_eattr[k] * D1C;
        } else {
            src = dst;
            eerow = meanproj;
        }
        const float* xlrow = xl + (size_t)src * D1C;
        float xlv[16];
        float sh0 = 0.f, sh1 = 0.f, sh2 = 0.f, sh3 = 0.f;
#pragma unroll
        for (int j = 0; j < 16; j++) {
            int c = lane + 32 * j;
            xlv[j] = xlrow[c];
            float z = xlv[j] + xrreg[j] + eerow[c];
            z = z > 0.f ? z : 0.2f * z;
            float p = z * attreg[j];
            if (j < 4) sh0 += p;
            else if (j < 8) sh1 += p;
            else if (j < 12) sh2 += p;
            else sh3 += p;
        }
#pragma unroll
        for (int o = 16; o; o >>= 1) {
            sh0 += __shfl_xor_sync(0xffffffffu, sh0, o);
            sh1 += __shfl_xor_sync(0xffffffffu, sh1, o);
            sh2 += __shfl_xor_sync(0xffffffffu, sh2, o);
            sh3 += __shfl_xor_sync(0xffffffffu, sh3, o);
        }
        float sv[4] = {sh0, sh1, sh2, sh3};
        float scale[4], w[4];
#pragma unroll
        for (int h = 0; h < 4; h++) {
            float nm = fmaxf(m[h], sv[h]);
            scale[h] = __expf(m[h] - nm);
            w[h] = __expf(sv[h] - nm);
            r[h] = r[h] * scale[h] + w[h];
            m[h] = nm;
        }
#pragma unroll
        for (int j = 0; j < 16; j++)
            acc[j] = acc[j] * scale[j >> 2] + w[j >> 2] * xlv[j];
    }
#pragma unroll
    for (int j = 0; j < 16; j++) {
        int c = lane + 32 * j;
        out[(size_t)dst * D1C + c] = acc[j] / (r[j >> 2] + 1e-16f) + bias[c];
    }
}

// ---------------- GAT layer-2 (all masks, compacted pairs) ----------------
__global__ void gat2_kernel(const float* __restrict__ xl, const float* __restrict__ xr,
                            const float* __restrict__ eproj,
                            const float* __restrict__ att, const float* __restrict__ bias,
                            float* __restrict__ out) {
    int p = blockIdx.x * 8 + (threadIdx.x >> 5);
    if (p >= g_pairofs[Aa]) return;
    int lane = threadIdx.x & 31;
    int packed = g_pair[p];
    int dst = packed & 0xFFFFF;
    int mi = packed >> 20;
    unsigned mbit = 1u << mi;
    const float* meanproj = g_meanproj2 + mi * D1C;

    float attreg[16], xrreg[16], acc[16];
    float m[4], r[4];
#pragma unroll
    for (int j = 0; j < 16; j++) {
        attreg[j] = att[(j >> 2) * 128 + lane + 32 * (j & 3)];
        xrreg[j] = xr[(size_t)dst * D1C + lane + 32 * j];
        acc[j] = 0.f;
    }
#pragma unroll
    for (int h = 0; h < 4; h++) { m[h] = -INFINITY; r[h] = 0.f; }

    int beg = g_offs[dst], end = g_offs[dst + 1];
    for (int k = beg; k <= end; k++) {
        int src;
        const float* eerow;
        if (k < end) {
            src = g_esrc[k];
            if (!(g_mask1[src] & mbit)) continue;
            eerow = eproj + (size_t)g_eattr[k] * D1C;
        } else {
            src = dst;
            eerow = meanproj;
        }
        const float* xlrow = xl + (size_t)src * D1C;
        float xlv[16];
        float sh0 = 0.f, sh1 = 0.f, sh2 = 0.f, sh3 = 0.f;
#pragma unroll
        for (int j = 0; j < 16; j++) {
            int c = lane + 32 * j;
            xlv[j] = xlrow[c];
            float z = xlv[j] + xrreg[j] + eerow[c];
            z = z > 0.f ? z : 0.2f * z;
            float pz = z * attreg[j];
            if (j < 4) sh0 += pz;
            else if (j < 8) sh1 += pz;
            else if (j < 12) sh2 += pz;
            else sh3 += pz;
        }
#pragma unroll
        for (int o = 16; o; o >>= 1) {
            sh0 += __shfl_xor_sync(0xffffffffu, sh0, o);
            sh1 += __shfl_xor_sync(0xffffffffu, sh1, o);
            sh2 += __shfl_xor_sync(0xffffffffu, sh2, o);
            sh3 += __shfl_xor_sync(0xffffffffu, sh3, o);
        }
        float sv[4] = {sh0, sh1, sh2, sh3};
        float scale[4], w[4];
#pragma unroll
        for (int h = 0; h < 4; h++) {
            float nm = fmaxf(m[h], sv[h]);
            scale[h] = __expf(m[h] - nm);
            w[h] = __expf(sv[h] - nm);
            r[h] = r[h] * scale[h] + w[h];
            m[h] = nm;
        }
#pragma unroll
        for (int j = 0; j < 16; j++)
            acc[j] = acc[j] * scale[j >> 2] + w[j >> 2] * xlv[j];
    }
#pragma unroll
    for (int j = 0; j < 16; j++) {
        int c = lane + 32 * j;
        out[(size_t)p * D1C + c] = acc[j] / (r[j >> 2] + 1e-16f) + bias[c];
    }
}

// ---------------- softmax aggregations (partials only) ----------------
__device__ __forceinline__ void online1(float v, float& m, float& r, float& w) {
    if (v <= m) {
        float ev = __expf(v - m);
        r += ev;
        w += ev * v;
    } else {
        float sc = __expf(m - v);
        r = r * sc + 1.f;
        w = w * sc + v;
        m = v;
    }
}

__global__ void aggAF_kernel(const float* __restrict__ x) {
    int c = threadIdx.x, b = blockIdx.x;
    const int chunk = (Nn + NBF - 1) / NBF;
    int n0 = b * chunk, n1 = min(n0 + chunk, Nn);
    float m = -INFINITY, r = 0.f, w = 0.f;
    for (int n = n0; n < n1; n++)
        online1(x[(size_t)n * D1C + c], m, r, w);
    g_partF[(b * 3 + 0) * D1C + c] = m;
    g_partF[(b * 3 + 1) * D1C + c] = r;
    g_partF[(b * 3 + 2) * D1C + c] = w;
}

__global__ void aggP_kernel(const float* __restrict__ x) {
    int c = threadIdx.x, b = blockIdx.x, i = blockIdx.y;
    int beg = g_pairofs[i], end = g_pairofs[i + 1];
    int cnt = end - beg;
    int chunk = (cnt + NBM - 1) / NBM;
    int r0 = beg + b * chunk, r1 = min(r0 + chunk, end);
    float m = -INFINITY, r = 0.f, w = 0.f;
    for (int p = r0; p < r1; p++)
        online1(x[(size_t)p * D1C + c], m, r, w);
    int idx = i * NBM + b;
    g_partM[(idx * 3 + 0) * D1C + c] = m;
    g_partM[(idx * 3 + 1) * D1C + c] = r;
    g_partM[(idx * 3 + 2) * D1C + c] = w;
}

// ---------------- HGT head (with fused final aggregations) ----------------
__device__ __forceinline__ float gelu_exact(float x) {
    return 0.5f * x * (1.f + erff(x * 0.70710678118654752f));
}

__global__ void head_kernel(const float* __restrict__ kqv_f, const float* __restrict__ kqvb_f,
                            const float* __restrict__ kqv_r, const float* __restrict__ kqvb_r,
                            const float* __restrict__ a_rel, const float* __restrict__ m_rel,
                            const float* __restrict__ p_rel,
                            const float* __restrict__ aW_f, const float* __restrict__ ab_f,
                            const float* __restrict__ aW_r, const float* __restrict__ ab_r,
                            const float* __restrict__ Wfr, const float* __restrict__ bfr,
                            const float* __restrict__ Wro, const float* __restrict__ bro,
                            float* __restrict__ out) {
    __shared__ float sF[512];
    __shared__ float BIG[4096];
    __shared__ float kf[64], vf[64];
    __shared__ float kr[512], qr[512], vr[512];
    __shared__ float kfa[64], kra[512];
    __shared__ float vfm0[64], vfm1[64], vrm2[512];
    __shared__ float aggr[512];
    __shared__ float outf[64], outr[512];
    __shared__ float red[32];
    __shared__ float scal[32];
    int t = threadIdx.x;

    // fused aggBF: frame_x from g_partF
    {
        int c = t;
        float gm = -INFINITY;
        for (int b = 0; b < NBF; b++) {
            float rr = g_partF[(b * 3 + 1) * D1C + c];
            if (rr > 0.f) gm = fmaxf(gm, g_partF[(b * 3 + 0) * D1C + c]);
        }
        float R = 0.f, W = 0.f;
        for (int b = 0; b < NBF; b++) {
            float rr = g_partF[(b * 3 + 1) * D1C + c];
            if (rr > 0.f) {
                float sc = __expf(g_partF[(b * 3 + 0) * D1C + c] - gm);
                R += rr * sc;
                W += g_partF[(b * 3 + 2) * D1C + c] * sc;
            }
        }
        sF[c] = W / R;
    }
    // fused aggBM: role_x rows from g_partM
    for (int idx = t; idx < Aa * D1C; idx += 512) {
        int i = idx / D1C, c = idx % D1C;
        float gm = -INFINITY;
        for (int b = 0; b < NBM; b++) {
            int pi = i * NBM + b;
            float rr = g_partM[(pi * 3 + 1) * D1C + c];
            if (rr > 0.f) gm = fmaxf(gm, g_partM[(pi * 3 + 0) * D1C + c]);
        }
        float R = 0.f, W = 0.f;
        for (int b = 0; b < NBM; b++) {
            int pi = i * NBM + b;
            float rr = g_partM[(pi * 3 + 1) * D1C + c];
            if (rr > 0.f) {
                float sc = __expf(g_partM[(pi * 3 + 0) * D1C + c] - gm);
                R += rr * sc;
                W += g_partM[(pi * 3 + 2) * D1C + c] * sc;
            }
        }
        BIG[idx] = W / R;
    }
    __syncthreads();

    if (t < 128) {
        int o = t & 63, sel = t >> 6;
        const float* Wm = kqv_f + (sel ? 2 : 0) * 512 * 64;
        float s = kqvb_f[(sel ? 2 : 0) * 64 + o];
        for (int c = 0; c < 512; c++) s += sF[c] * Wm[c * 64 + o];
        if (sel) vf[o] = s; else kf[o] = s;
    }
    for (int idx = t; idx < 1536; idx += 512) {
        int a = idx / 192, rem = idx % 192, rsel = rem >> 6, o = rem & 63;
        const float* Wm = kqv_r + rsel * 512 * 64;
        float s = kqvb_r[rsel * 64 + o];
        const float* rx = BIG + a * 512;
        for (int c = 0; c < 512; c++) s += rx[c] * Wm[c * 64 + o];
        (rsel == 0 ? kr : rsel == 1 ? qr : vr)[a * 64 + o] = s;
    }
    __syncthreads();

    for (int o = t; o < 64; o += 512) {
        float s1 = 0.f, s2 = 0.f, s3 = 0.f;
        for (int c = 0; c < 64; c++) {
            s1 += kf[c] * a_rel[1 * 4096 + c * 64 + o];
            s2 += vf[c] * m_rel[0 * 4096 + c * 64 + o];
            s3 += vf[c] * m_rel[1 * 4096 + c * 64 + o];
        }
        kfa[o] = s1; vfm0[o] = s2; vfm1[o] = s3;
    }
    for (int idx = t; idx < 512; idx += 512) {
        int a = idx >> 6, o = idx & 63;
        float s1 = 0.f, s2 = 0.f;
        for (int c = 0; c < 64; c++) {
            s1 += kr[a * 64 + c] * a_rel[2 * 4096 + c * 64 + o];
            s2 += vr[a * 64 + c] * m_rel[2 * 4096 + c * 64 + o];
        }
        kra[idx] = s1; vrm2[idx] = s2;
    }
    __syncthreads();

    if (t < 8) {
        float sq = 0.125f;
        float sfr = 0.f, srr = 0.f;
        for (int o = 0; o < 64; o++) {
            sfr += qr[t * 64 + o] * kfa[o];
            srr += qr[t * 64 + o] * kra[t * 64 + o];
        }
        sfr *= sq * p_rel[1];
        srr *= sq * p_rel[2];
        float mx = fmaxf(sfr, srr);
        float e0 = __expf(sfr - mx), e1 = __expf(srr - mx);
        float den = e0 + e1;
        scal[2 * t] = e0 / den;
        scal[2 * t + 1] = e1 / den;
    }
    __syncthreads();

    if (t < 64) vfm0[t] = gelu_exact(vfm0[t]);
    {
        int a = t >> 6, o = t & 63;
        float v = scal[2 * a] * vfm1[o] + scal[2 * a + 1] * vrm2[t];
        aggr[t] = gelu_exact(v);
    }
    __syncthreads();

    if (t < 64) {
        float s = ab_f[t];
        for (int o = 0; o < 64; o++) s += vfm0[o] * aW_f[o * 64 + t];
        outf[t] = s;
    }
    {
        int a = t >> 6, o2 = t & 63;
        float s = ab_r[o2];
        for (int o = 0; o < 64; o++) s += aggr[a * 64 + o] * aW_r[o * 64 + o2];
        outr[t] = s;
    }
    __syncthreads();

    float* fl = BIG;
    float* rl = BIG + 2048;
    for (int f = t; f < NFC; f += 512) {
        float s = bfr[f];
        for (int o = 0; o < 64; o++) s += outf[o] * Wfr[o * NFC + f];
        fl[f] = s;
    }
    {
        int a = t >> 6, rr = t & 63;
        float s = bro[rr];
        for (int o = 0; o < 64; o++) s += outr[a * 64 + o] * Wro[o * NRC + rr];
        rl[t] = s;
    }
    __syncthreads();

    float lm = -INFINITY;
    for (int f = t; f < NFC; f += 512) lm = fmaxf(lm, fl[f]);
#pragma unroll
    for (int o = 16; o; o >>= 1) lm = fmaxf(lm, __shfl_xor_sync(0xffffffffu, lm, o));
    if ((t & 31) == 0) red[t >> 5] = lm;
    __syncthreads();
    if (t < 16) {
        float x = red[t];
#pragma unroll
        for (int o = 8; o; o >>= 1) x = fmaxf(x, __shfl_xor_sync(0xffffu, x, o));
        if (t == 0) red[0] = x;
    }
    __syncthreads();
    float gmax = red[0];
    __syncthreads();
    float ls = 0.f;
    for (int f = t; f < NFC; f += 512) ls += __expf(fl[f] - gmax);
#pragma unroll
    for (int o = 16; o; o >>= 1) ls += __shfl_xor_sync(0xffffffffu, ls, o);
    if ((t & 31) == 0) red[t >> 5] = ls;
    __syncthreads();
    if (t < 16) {
        float x = red[t];
#pragma unroll
        for (int o = 8; o; o >>= 1) x += __shfl_xor_sync(0xffffu, x, o);
        if (t == 0) red[0] = x;
    }
    __syncthreads();
    float lse = gmax + logf(red[0]);
    for (int f = t; f < NFC; f += 512) out[f] = fl[f] - lse;

    if (t < 8) {
        float mx = -INFINITY;
        for (int i = 0; i < 64; i++) mx = fmaxf(mx, rl[t * 64 + i]);
        float s = 0.f;
        for (int i = 0; i < 64; i++) s += __expf(rl[t * 64 + i] - mx);
        scal[t] = mx + logf(s);
    }
    __syncthreads();
    {
        int a = t >> 6;
        out[NFC + t] = rl[t] - scal[a];
    }
}

// ---------------- launch: 4-way fork-join DAG ----------------
extern "C" void kernel_launch(void* const* d_in, const int* in_sizes, int n_in,
                              void* d_out, int out_size) {
    const int* node_pred = (const int*)d_in[0];
    const int* ei = (const int*)d_in[1];
    const int* eattr = (const int*)d_in[2];
    const int* args = (const int*)d_in[3];
    const float* pred_emb = (const float*)d_in[4];
    const float* Wl1 = (const float*)d_in[5];
    const float* Wr1 = (const float*)d_in[6];
    const float* We1 = (const float*)d_in[7];
    const float* att1 = (const float*)d_in[8];
    const float* b1 = (const float*)d_in[9];
    const float* Wl2 = (const float*)d_in[10];
    const float* Wr2 = (const float*)d_in[11];
    const float* We2 = (const float*)d_in[12];
    const float* att2 = (const float*)d_in[13];
    const float* b2 = (const float*)d_in[14];
    const float* kqv_f = (const float*)d_in[15];
    const float* kqvb_f = (const float*)d_in[16];
    const float* kqv_r = (const float*)d_in[17];
    const float* kqvb_r = (const float*)d_in[18];
    const float* a_rel = (const float*)d_in[19];
    const float* m_rel = (const float*)d_in[20];
    const float* p_rel = (const float*)d_in[21];
    const float* aW_f = (const float*)d_in[22];
    const float* ab_f = (const float*)d_in[23];
    const float* aW_r = (const float*)d_in[24];
    const float* ab_r = (const float*)d_in[25];
    const float* Wfr = (const float*)d_in[26];
    const float* bfr = (const float*)d_in[27];
    const float* Wro = (const float*)d_in[28];
    const float* bro = (const float*)d_in[29];
    float* out = (float*)d_out;

    float *p_xl1, *p_xr1, *p_xl2, *p_xr2, *p_h, *p_hbuf2;
    float *p_ep1, *p_ep2, *p_mp1;
    __nv_bfloat16 *p_bh1, *p_bl1, *p_bh2, *p_bl2;
    cudaGetSymbolAddress((void**)&p_xl1, g_xl1);
    cudaGetSymbolAddress((void**)&p_xr1, g_xr1);
    cudaGetSymbolAddress((void**)&p_xl2, g_xl2);
    cudaGetSymbolAddress((void**)&p_xr2, g_xr2);
    cudaGetSymbolAddress((void**)&p_h, g_h);
    cudaGetSymbolAddress((void**)&p_hbuf2, g_hbuf2);
    cudaGetSymbolAddress((void**)&p_ep1, g_eproj1);
    cudaGetSymbolAddress((void**)&p_ep2, g_eproj2);
    cudaGetSymbolAddress((void**)&p_mp1, g_meanproj1);
    cudaGetSymbolAddress((void**)&p_bh1, g_Bh1);
    cudaGetSymbolAddress((void**)&p_bl1, g_Bl1);
    cudaGetSymbolAddress((void**)&p_bh2, g_Bh2);
    cudaGetSymbolAddress((void**)&p_bl2, g_Bl2);

    cudaFuncSetAttribute(mma_gemm_kernel, cudaFuncAttributeMaxDynamicSharedMemorySize, GDYN);

    static cudaStream_t s1 = nullptr, s2 = nullptr, s3 = nullptr;
    static cudaEvent_t eStart = nullptr, eZ = nullptr, eE = nullptr, eW2 = nullptr;
    static cudaEvent_t eS1 = nullptr, eS2 = nullptr, eG1 = nullptr, eF = nullptr;
    if (s1 == nullptr) {
        cudaStreamCreateWithFlags(&s1, cudaStreamNonBlocking);
        cudaStreamCreateWithFlags(&s2, cudaStreamNonBlocking);
        cudaStreamCreateWithFlags(&s3, cudaStreamNonBlocking);
        cudaEventCreateWithFlags(&eStart, cudaEventDisableTiming);
        cudaEventCreateWithFlags(&eZ, cudaEventDisableTiming);
        cudaEventCreateWithFlags(&eE, cudaEventDisableTiming);
        cudaEventCreateWithFlags(&eW2, cudaEventDisableTiming);
        cudaEventCreateWithFlags(&eS1, cudaEventDisableTiming);
        cudaEventCreateWithFlags(&eS2, cudaEventDisableTiming);
        cudaEventCreateWithFlags(&eG1, cudaEventDisableTiming);
        cudaEventCreateWithFlags(&eF, cudaEventDisableTiming);
    }

    cudaEventRecord(eStart, 0);

    // main: zero -> wsplit1 -> gemm1
    zeroK_kernel<<<20, 512>>>();
    cudaEventRecord(eZ, 0);
    wsplit1_kernel<<<256, 512>>>(Wl1, Wr1);
    mma_gemm_kernel<<<dim3(79, 8), 256, GDYN>>>(pred_emb, node_pred, p_bh1, p_bl1, p_xl1, p_xr1, EMBC);

    // s3: eproj -> wsplit2
    cudaStreamWaitEvent(s3, eStart, 0);
    eproj_kernel<<<64, 512, 0, s3>>>(pred_emb, We1, We2);
    cudaEventRecord(eE, s3);
    wsplit2_kernel<<<1024, 512, 0, s3>>>(Wl2, Wr2);
    cudaEventRecord(eW2, s3);

    // s1: deg -> scan -> fill -> histF -> meanprojF
    cudaStreamWaitEvent(s1, eZ, 0);
    degK_kernel<<<625, 256, 0, s1>>>(ei);
    scan_kernel<<<1, 1024, 0, s1>>>();
    fill_kernel<<<625, 256, 0, s1>>>(ei, eattr);
    histF_kernel<<<128, 256, 0, s1>>>(eattr);
    cudaStreamWaitEvent(s1, eE, 0);
    meanprojF_kernel<<<1, 512, 0, s1>>>();
    cudaEventRecord(eS1, s1);

    // s2: seed -> BFS x3 -> histM -> meanprojM -> pairscan
    cudaStreamWaitEvent(s2, eZ, 0);
    seedK_kernel<<<1, 32, 0, s2>>>(args);
    copy_mask_kernel<<<20, 512, 0, s2>>>(0);
    hop_kernel<<<625, 256, 0, s2>>>(ei, 0);
    copy_mask_kernel<<<20, 512, 0, s2>>>(1);
    hop_kernel<<<625, 256, 0, s2>>>(ei, 1);
    copy_mask_kernel<<<20, 512, 0, s2>>>(0);
    hop_kernel<<<625, 256, 0, s2>>>(ei, 0);
    histM_kernel<<<128, 256, 0, s2>>>(ei, eattr);
    cudaStreamWaitEvent(s2, eE, 0);
    meanprojM_kernel<<<Aa, 512, 0, s2>>>();
    pairscan_kernel<<<1, 1024, 0, s2>>>();
    cudaEventRecord(eS2, s2);

    // main: gat1 (needs CSR/histF/meanprojF + gemm1)
    cudaStreamWaitEvent(0, eS1, 0);
    gat1_kernel<<<1250, 256>>>(p_xl1, p_xr1, p_ep1, p_mp1, att1, b1, p_h);
    cudaEventRecord(eG1, 0);

    // s1: frame partials (overlaps gemm2/gat2)
    cudaStreamWaitEvent(s1, eG1, 0);
    aggAF_kernel<<<NBF, 512, 0, s1>>>(p_h);
    cudaEventRecord(eF, s1);

    // main: gemm2 -> gat2 -> aggP -> head
    cudaStreamWaitEvent(0, eW2, 0);
    mma_gemm_kernel<<<dim3(79, 8), 256, GDYN>>>(p_h, nullptr, p_bh2, p_bl2, p_xl2, p_xr2, D1C);
    cudaStreamWaitEvent(0, eS2, 0);
    gat2_kernel<<<Nn, 256>>>(p_xl2, p_xr2, p_ep2, att2, b2, p_hbuf2);
    aggP_kernel<<<dim3(NBM, Aa), 512>>>(p_hbuf2);
    cudaStreamWaitEvent(0, eF, 0);
    head_kernel<<<1, 512>>>(kqv_f, kqvb_f, kqv_r, kqvb_r, a_rel, m_rel, p_rel,
                            aW_f, ab_f, aW_r, ab_r, Wfr, bfr, Wro, bro, out);
}

// round 9
// speedup vs baseline: 1.0538x; 1.0538x over previous
#include <cuda_runtime.h>
#include <cuda_bf16.h>
#include <math.h>
#include <stdint.h>

#define Nn 10000
#define NnPad 10112
#define Ee 160000
#define Aa 8
#define D1C 512
#define EMBC 128
#define ATTRC 64
#define NFC 1500
#define NRC 64
#define NBM 16
#define NBF 64

// ---------------- device scratch ----------------
__device__ __align__(16) float g_xl1[Nn * D1C];
__device__ __align__(16) float g_xr1[Nn * D1C];
__device__ __align__(16) float g_h[Nn * D1C];
__device__ __align__(16) float g_xl2[Nn * D1C];
__device__ __align__(16) float g_xr2[Nn * D1C];
__device__ __align__(16) float g_hbuf2[Aa * Nn * D1C];
__device__ __align__(16) float g_eproj1[ATTRC * D1C];
__device__ __align__(16) float g_eproj2[ATTRC * D1C];
__device__ __align__(16) float g_meanproj1[D1C];
__device__ __align__(16) float g_meanproj2[Aa * D1C];
__device__ int   g_deg[Nn];
__device__ int   g_offs[Nn + 1];
__device__ int   g_cursor[Nn];
__device__ int   g_esrc[Ee];
__device__ int   g_eattr[Ee];
__device__ unsigned g_mask0[Nn];
__device__ unsigned g_mask1[Nn];
__device__ int   g_histF[ATTRC];
__device__ int   g_histM[Aa * ATTRC];
__device__ int   g_pairofs[Aa + 1];
__device__ int   g_pair[Aa * Nn];
__device__ float g_partM[Aa * NBM * 3 * D1C];
__device__ float g_partF[NBF * 3 * D1C];
// bf16 hi/lo split operands (padded rows for cp.async overreach)
__device__ __align__(16) __nv_bfloat16 g_Ah1[NnPad * EMBC];
__device__ __align__(16) __nv_bfloat16 g_Al1[NnPad * EMBC];
__device__ __align__(16) __nv_bfloat16 g_Hh[NnPad * D1C];
__device__ __align__(16) __nv_bfloat16 g_Hl[NnPad * D1C];
__device__ __align__(16) __nv_bfloat16 g_Bh1[1024 * EMBC];
__device__ __align__(16) __nv_bfloat16 g_Bl1[1024 * EMBC];
__device__ __align__(16) __nv_bfloat16 g_Bh2[1024 * D1C];
__device__ __align__(16) __nv_bfloat16 g_Bl2[1024 * D1C];

// ---------------- asm helpers ----------------
__device__ __forceinline__ uint32_t smem_u32(const void* p) {
    uint32_t a;
    asm("{ .reg .u64 t; cvta.to.shared.u64 t, %1; cvt.u32.u64 %0, t; }" : "=r"(a) : "l"(p));
    return a;
}
__device__ __forceinline__ void ldsm4(uint32_t& r0, uint32_t& r1, uint32_t& r2, uint32_t& r3, uint32_t addr) {
    asm volatile("ldmatrix.sync.aligned.m8n8.x4.shared.b16 {%0,%1,%2,%3}, [%4];"
                 : "=r"(r0), "=r"(r1), "=r"(r2), "=r"(r3) : "r"(addr));
}
__device__ __forceinline__ void mma16816(float* c, const uint32_t* a, const uint32_t* b) {
    asm volatile("mma.sync.aligned.m16n8k16.row.col.f32.bf16.bf16.f32 "
                 "{%0,%1,%2,%3}, {%4,%5,%6,%7}, {%8,%9}, {%0,%1,%2,%3};"
                 : "+f"(c[0]), "+f"(c[1]), "+f"(c[2]), "+f"(c[3])
                 : "r"(a[0]), "r"(a[1]), "r"(a[2]), "r"(a[3]), "r"(b[0]), "r"(b[1]));
}
__device__ __forceinline__ void cp16(uint32_t dst, const void* src) {
    asm volatile("cp.async.cg.shared.global [%0], [%1], 16;" :: "r"(dst), "l"(src));
}
#define CP_COMMIT() asm volatile("cp.async.commit_group;")
#define CP_WAIT1()  asm volatile("cp.async.wait_group 1;")
#define CP_WAIT0()  asm volatile("cp.async.wait_group 0;")

// ---------------- prep kernels ----------------
__global__ void zeroK_kernel() {
    int i = blockIdx.x * 512 + threadIdx.x;
    if (i < Nn) { g_deg[i] = 0; g_mask0[i] = 0u; }
    if (i < ATTRC) g_histF[i] = 0;
    if (i < Aa * ATTRC) g_histM[i] = 0;
}

// coalesced transpose + bf16 hi/lo split: out[nOff+n][k] = W[k][n]
__global__ void wsplitT_kernel(const float* __restrict__ W,
                               __nv_bfloat16* __restrict__ oh, __nv_bfloat16* __restrict__ ol,
                               int K, int nOff) {
    __shared__ float tile[32][33];
    int k0 = blockIdx.x * 32, n0 = blockIdx.y * 32;
    int tx = threadIdx.x & 31, ty = threadIdx.x >> 5;
#pragma unroll
    for (int i = 0; i < 4; i++)
        tile[ty + i * 8][tx] = W[(size_t)(k0 + ty + i * 8) * 512 + n0 + tx];
    __syncthreads();
#pragma unroll
    for (int i = 0; i < 4; i++) {
        int n = n0 + ty + i * 8, k = k0 + tx;
        float v = tile[tx][ty + i * 8];
        __nv_bfloat16 h = __float2bfloat16(v);
        oh[(size_t)(nOff + n) * K + k] = h;
        ol[(size_t)(nOff + n) * K + k] = __float2bfloat16(v - __bfloat162float(h));
    }
}

// gather pred_emb rows by node_pred and split to bf16 hi/lo
__global__ void gsplit1_kernel(const float* __restrict__ pe, const int* __restrict__ np) {
    int idx = blockIdx.x * 256 + threadIdx.x;   // Nn*32 float4 groups
    if (idx >= Nn * 32) return;
    int row = idx >> 5, k4 = idx & 31;
    float4 v = *(const float4*)(pe + (size_t)np[row] * EMBC + (k4 << 2));
    __nv_bfloat16 h0 = __float2bfloat16(v.x), h1 = __float2bfloat16(v.y);
    __nv_bfloat16 h2 = __float2bfloat16(v.z), h3 = __float2bfloat16(v.w);
    __nv_bfloat162 hA = __halves2bfloat162(h0, h1), hB = __halves2bfloat162(h2, h3);
    __nv_bfloat162 lA = __halves2bfloat162(__float2bfloat16(v.x - __bfloat162float(h0)),
                                           __float2bfloat16(v.y - __bfloat162float(h1)));
    __nv_bfloat162 lB = __halves2bfloat162(__float2bfloat16(v.z - __bfloat162float(h2)),
                                           __float2bfloat16(v.w - __bfloat162float(h3)));
    *(uint2*)(g_Ah1 + (size_t)row * EMBC + (k4 << 2)) = make_uint2(*(uint32_t*)&hA, *(uint32_t*)&hB);
    *(uint2*)(g_Al1 + (size_t)row * EMBC + (k4 << 2)) = make_uint2(*(uint32_t*)&lA, *(uint32_t*)&lB);
}

__global__ void eproj_kernel(const float* __restrict__ pe,
                             const float* __restrict__ We1,
                             const float* __restrict__ We2) {
    int b = blockIdx.x, c = threadIdx.x;
    int a = b & 63;
    bool second = b >= 64;
    __shared__ float row[EMBC];
    if (c < EMBC) row[c] = pe[a * EMBC + c];
    __syncthreads();
    const float* W = second ? We2 : We1;
    float s = 0.f;
#pragma unroll 8
    for (int k = 0; k < EMBC; k++) s += row[k] * W[k * D1C + c];
    (second ? g_eproj2 : g_eproj1)[a * D1C + c] = s;
}

__global__ void degK_kernel(const int* __restrict__ ei) {
    int e = blockIdx.x * 256 + threadIdx.x;
    if (e < Ee) atomicAdd(&g_deg[ei[Ee + e]], 1);
}

__global__ void seedK_kernel(const int* __restrict__ args) {
    if (threadIdx.x < Aa) atomicOr(&g_mask0[args[threadIdx.x]], 1u << threadIdx.x);
}

__global__ void copy_mask_kernel(int dir) {
    int i = blockIdx.x * 512 + threadIdx.x;
    if (i < Nn) {
        if (dir == 0) g_mask1[i] = g_mask0[i];
        else          g_mask0[i] = g_mask1[i];
    }
}

__global__ void hop_kernel(const int* __restrict__ ei, int dir) {
    int e = blockIdx.x * blockDim.x + threadIdx.x;
    if (e >= Ee) return;
    int s = ei[e], d = ei[Ee + e];
    const unsigned* cur = dir == 0 ? g_mask0 : g_mask1;
    unsigned* nxt = dir == 0 ? g_mask1 : g_mask0;
    unsigned m = cur[d];
    if (m) atomicOr(&nxt[s], m);
}

__global__ void histF_kernel(const int* __restrict__ attr) {
    __shared__ int shF[ATTRC];
    int t = threadIdx.x;
    if (t < ATTRC) shF[t] = 0;
    __syncthreads();
    for (int e = blockIdx.x * blockDim.x + t; e < Ee; e += gridDim.x * blockDim.x)
        atomicAdd(&shF[attr[e]], 1);
    __syncthreads();
    if (t < ATTRC && shF[t]) atomicAdd(&g_histF[t], shF[t]);
}

__global__ void histM_kernel(const int* __restrict__ ei, const int* __restrict__ attr) {
    __shared__ int shM[Aa * ATTRC];
    int t = threadIdx.x;
    for (int i = t; i < Aa * ATTRC; i += blockDim.x) shM[i] = 0;
    __syncthreads();
    for (int e = blockIdx.x * blockDim.x + t; e < Ee; e += gridDim.x * blockDim.x) {
        int a = attr[e];
        unsigned mb = g_mask1[ei[e]] & g_mask1[ei[Ee + e]];
        while (mb) {
            int i = __ffs(mb) - 1;
            mb &= mb - 1;
            atomicAdd(&shM[i * ATTRC + a], 1);
        }
    }
    __syncthreads();
    for (int i = t; i < Aa * ATTRC; i += blockDim.x) if (shM[i]) atomicAdd(&g_histM[i], shM[i]);
}

__global__ void meanprojF_kernel() {
    int c = threadIdx.x;
    float s = 0.f, tot = 0.f;
    for (int a = 0; a < ATTRC; a++) {
        float hh = (float)g_histF[a];
        tot += hh;
        s += hh * g_eproj1[a * D1C + c];
    }
    g_meanproj1[c] = s / fmaxf(tot, 1.f);
}

__global__ void meanprojM_kernel() {
    int i = blockIdx.x, c = threadIdx.x;
    float s = 0.f, tot = 0.f;
    for (int a = 0; a < ATTRC; a++) {
        float hh = (float)g_histM[i * ATTRC + a];
        tot += hh;
        s += hh * g_eproj2[a * D1C + c];
    }
    g_meanproj2[i * D1C + c] = s / fmaxf(tot, 1.f);
}

// ---------------- pair compaction ----------------
__global__ void pairscan_kernel() {
    __shared__ unsigned long long shA[1024], shB[1024];
    int t = threadIdx.x;
    int base = t * 10;
    unsigned mloc[10];
    unsigned long long a = 0, bv = 0;
#pragma unroll
    for (int i = 0; i < 10; i++) {
        int idx = base + i;
        unsigned mm = (idx < Nn) ? g_mask1[idx] : 0u;
        mloc[i] = mm;
#pragma unroll
        for (int b = 0; b < 4; b++) a += (unsigned long long)((mm >> b) & 1u) << (16 * b);
#pragma unroll
        for (int b = 0; b < 4; b++) bv += (unsigned long long)((mm >> (b + 4)) & 1u) << (16 * b);
    }
    shA[t] = a; shB[t] = bv;
    __syncthreads();
    for (int off = 1; off < 1024; off <<= 1) {
        unsigned long long va = (t >= off) ? shA[t - off] : 0ULL;
        unsigned long long vb = (t >= off) ? shB[t - off] : 0ULL;
        __syncthreads();
        shA[t] += va; shB[t] += vb;
        __syncthreads();
    }
    unsigned long long totA = shA[1023], totB = shB[1023];
    int ofs[Aa + 1];
    ofs[0] = 0;
#pragma unroll
    for (int b = 0; b < 4; b++) ofs[b + 1] = ofs[b] + (int)((totA >> (16 * b)) & 0xFFFF);
#pragma unroll
    for (int b = 4; b < 8; b++) ofs[b + 1] = ofs[b] + (int)((totB >> (16 * (b - 4))) & 0xFFFF);
    if (t == 0)
        for (int b = 0; b <= Aa; b++) g_pairofs[b] = ofs[b];
    unsigned long long exA = shA[t] - a, exB = shB[t] - bv;
    int cur[8];
#pragma unroll
    for (int b = 0; b < 4; b++) cur[b] = ofs[b] + (int)((exA >> (16 * b)) & 0xFFFF);
#pragma unroll
    for (int b = 4; b < 8; b++) cur[b] = ofs[b] + (int)((exB >> (16 * (b - 4))) & 0xFFFF);
#pragma unroll
    for (int i = 0; i < 10; i++) {
        int idx = base + i;
        if (idx < Nn) {
            unsigned mm = mloc[i];
            while (mm) {
                int b = __ffs(mm) - 1;
                mm &= mm - 1;
                g_pair[cur[b]++] = idx | (b << 20);
            }
        }
    }
}

// ---------------- pipelined HMMA GEMM (bf16 hi/lo inputs, cp.async 2-stage) ----
#define GSTRIDE2 144                       // bytes per row (72 bf16)
#define GTILE (128 * GSTRIDE2)             // 18432
#define GSTAGE (4 * GTILE)                 // Ah Al Bh Bl
#define GDYN (2 * GSTAGE)                  // 147456

__global__ void __launch_bounds__(256, 1)
mma_gemm_kernel(const __nv_bfloat16* __restrict__ Ah, const __nv_bfloat16* __restrict__ Al,
                const __nv_bfloat16* __restrict__ Bh, const __nv_bfloat16* __restrict__ Bl,
                float* __restrict__ Cl, float* __restrict__ Cr, int K) {
    extern __shared__ char dyn[];
    const int tid = threadIdx.x, wid = tid >> 5, lane = tid & 31;
    const int warp_m = wid & 1, warp_n = wid >> 1;
    const int row0 = blockIdx.x * 128;
    const int coltile = blockIdx.y;
    const uint32_t sbase = smem_u32(dyn);

    float acc[4][4][4];
#pragma unroll
    for (int mi = 0; mi < 4; mi++)
#pragma unroll
        for (int ni = 0; ni < 4; ni++)
#pragma unroll
            for (int q = 0; q < 4; q++) acc[mi][ni][q] = 0.f;

    const int lrow = tid >> 3, lk16 = tid & 7;
    const int nch = K >> 6;

    auto load_chunk = [&](int ch, int st) {
        uint32_t s0 = sbase + st * GSTAGE;
#pragma unroll
        for (int it = 0; it < 4; it++) {
            int row = lrow + it * 32;
            uint32_t doff = row * GSTRIDE2 + lk16 * 16;
            size_t aofs = (size_t)(row0 + row) * K + ch * 64 + lk16 * 8;
            size_t bofs = (size_t)(coltile * 128 + row) * K + ch * 64 + lk16 * 8;
            cp16(s0 + doff, Ah + aofs);
            cp16(s0 + GTILE + doff, Al + aofs);
            cp16(s0 + 2 * GTILE + doff, Bh + bofs);
            cp16(s0 + 3 * GTILE + doff, Bl + bofs);
        }
    };

    const int lane15 = lane & 15, khalfA = lane >> 4;
    const int nrow = (lane & 7) | ((lane >> 4) << 3), khB = (lane >> 3) & 1;

    load_chunk(0, 0);
    CP_COMMIT();

    for (int ch = 0; ch < nch; ch++) {
        if (ch + 1 < nch) {
            load_chunk(ch + 1, (ch + 1) & 1);
            CP_COMMIT();
            CP_WAIT1();
        } else {
            CP_WAIT0();
        }
        __syncthreads();
        uint32_t s0 = sbase + (ch & 1) * GSTAGE;
        uint32_t sAh = s0, sAl = s0 + GTILE, sBh = s0 + 2 * GTILE, sBl = s0 + 3 * GTILE;
#pragma unroll
        for (int ks = 0; ks < 4; ks++) {
            int k0 = ks * 16;
            uint32_t ah[4][4], al[4][4], bh[2][4], bl[2][4];
#pragma unroll
            for (int mi = 0; mi < 4; mi++) {
                uint32_t ro = (warp_m * 64 + mi * 16 + lane15) * GSTRIDE2 + k0 * 2 + khalfA * 16;
                ldsm4(ah[mi][0], ah[mi][1], ah[mi][2], ah[mi][3], sAh + ro);
                ldsm4(al[mi][0], al[mi][1], al[mi][2], al[mi][3], sAl + ro);
            }
#pragma unroll
            for (int pr = 0; pr < 2; pr++) {
                uint32_t ro = (warp_n * 32 + pr * 16 + nrow) * GSTRIDE2 + k0 * 2 + khB * 16;
                ldsm4(bh[pr][0], bh[pr][1], bh[pr][2], bh[pr][3], sBh + ro);
                ldsm4(bl[pr][0], bl[pr][1], bl[pr][2], bl[pr][3], sBl + ro);
            }
#pragma unroll
            for (int mi = 0; mi < 4; mi++)
#pragma unroll
                for (int ni = 0; ni < 4; ni++) {
                    int pr = ni >> 1, ix = (ni & 1) * 2;
                    uint32_t bhv[2] = {bh[pr][ix], bh[pr][ix + 1]};
                    uint32_t blv[2] = {bl[pr][ix], bl[pr][ix + 1]};
                    mma16816(acc[mi][ni], ah[mi], bhv);
                    mma16816(acc[mi][ni], ah[mi], blv);
                    mma16816(acc[mi][ni], al[mi], bhv);
                }
        }
        __syncthreads();
    }

    float* dstbase;
    int colbase;
    if (coltile < 4) { dstbase = Cl; colbase = coltile * 128; }
    else             { dstbase = Cr; colbase = (coltile - 4) * 128; }
    colbase += warp_n * 32;
#pragma unroll
    for (int mi = 0; mi < 4; mi++) {
        int r0r = row0 + warp_m * 64 + mi * 16 + (lane >> 2);
#pragma unroll
        for (int ni = 0; ni < 4; ni++) {
            int cc = colbase + ni * 8 + (lane & 3) * 2;
            if (r0r < Nn)
                *(float2*)(dstbase + (size_t)r0r * 512 + cc) = make_float2(acc[mi][ni][0], acc[mi][ni][1]);
            if (r0r + 8 < Nn)
                *(float2*)(dstbase + (size_t)(r0r + 8) * 512 + cc) = make_float2(acc[mi][ni][2], acc[mi][ni][3]);
        }
    }
}

// ---------------- CSR scan/fill ----------------
__global__ void scan_kernel() {
    __shared__ int sh[1024];
    int t = threadIdx.x;
    int base = t * 10;
    int loc[10];
    int s = 0;
#pragma unroll
    for (int i = 0; i < 10; i++) {
        int idx = base + i;
        loc[i] = (idx < Nn) ? g_deg[idx] : 0;
        s += loc[i];
    }
    sh[t] = s;
    __syncthreads();
    for (int off = 1; off < 1024; off <<= 1) {
        int v = (t >= off) ? sh[t - off] : 0;
        __syncthreads();
        sh[t] += v;
        __syncthreads();
    }
    int run = (t > 0) ? sh[t - 1] : 0;
#pragma unroll
    for (int i = 0; i < 10; i++) {
        int idx = base + i;
        if (idx < Nn) {
            g_offs[idx] = run;
            g_cursor[idx] = run;
            run += loc[i];
        }
    }
    if (t == 0) g_offs[Nn] = Ee;
}

__global__ void fill_kernel(const int* __restrict__ ei, const int* __restrict__ attr) {
    int e = blockIdx.x * blockDim.x + threadIdx.x;
    if (e >= Ee) return;
    int d = ei[Ee + e];
    int pos = atomicAdd(&g_cursor[d], 1);
    g_esrc[pos] = ei[e];
    g_eattr[pos] = attr[e];
}

// ---------------- GAT layer-1 (also emits bf16 hi/lo of h) ----------------
__global__ void gat1_kernel(const float* __restrict__ xl, const float* __restrict__ xr,
                            const float* __restrict__ eproj, const float* __restrict__ meanproj,
                            const float* __restrict__ att, const float* __restrict__ bias,
                            float* __restrict__ out) {
    int warp = threadIdx.x >> 5;
    int lane = threadIdx.x & 31;
    int dst = blockIdx.x * 8 + warp;
    if (dst >= Nn) return;

    float attreg[16], xrreg[16], acc[16];
    float m[4], r[4];
#pragma unroll
    for (int j = 0; j < 16; j++) {
        attreg[j] = att[(j >> 2) * 128 + lane + 32 * (j & 3)];
        xrreg[j] = xr[(size_t)dst * D1C + lane + 32 * j];
        acc[j] = 0.f;
    }
#pragma unroll
    for (int h = 0; h < 4; h++) { m[h] = -INFINITY; r[h] = 0.f; }

    int beg = g_offs[dst], end = g_offs[dst + 1];
    for (int k = beg; k <= end; k++) {
        int src;
        const float* eerow;
        if (k < end) {
            src = g_esrc[k];
            eerow = eproj + (size_t)g_eattr[k] * D1C;
        } else {
            src = dst;
            eerow = meanproj;
        }
        const float* xlrow = xl + (size_t)src * D1C;
        float xlv[16];
        float sh0 = 0.f, sh1 = 0.f, sh2 = 0.f, sh3 = 0.f;
#pragma unroll
        for (int j = 0; j < 16; j++) {
            int c = lane + 32 * j;
            xlv[j] = xlrow[c];
            float z = xlv[j] + xrreg[j] + eerow[c];
            z = z > 0.f ? z : 0.2f * z;
            float p = z * attreg[j];
            if (j < 4) sh0 += p;
            else if (j < 8) sh1 += p;
            else if (j < 12) sh2 += p;
            else sh3 += p;
        }
#pragma unroll
        for (int o = 16; o; o >>= 1) {
            sh0 += __shfl_xor_sync(0xffffffffu, sh0, o);
            sh1 += __shfl_xor_sync(0xffffffffu, sh1, o);
            sh2 += __shfl_xor_sync(0xffffffffu, sh2, o);
            sh3 += __shfl_xor_sync(0xffffffffu, sh3, o);
        }
        float sv[4] = {sh0, sh1, sh2, sh3};
        float scale[4], w[4];
#pragma unroll
        for (int h = 0; h < 4; h++) {
            float nm = fmaxf(m[h], sv[h]);
            scale[h] = __expf(m[h] - nm);
            w[h] = __expf(sv[h] - nm);
            r[h] = r[h] * scale[h] + w[h];
            m[h] = nm;
        }
#pragma unroll
        for (int j = 0; j < 16; j++)
            acc[j] = acc[j] * scale[j >> 2] + w[j >> 2] * xlv[j];
    }
#pragma unroll
    for (int j = 0; j < 16; j++) {
        int c = lane + 32 * j;
        float v = acc[j] / (r[j >> 2] + 1e-16f) + bias[c];
        out[(size_t)dst * D1C + c] = v;
        __nv_bfloat16 hv = __float2bfloat16(v);
        g_Hh[(size_t)dst * D1C + c] = hv;
        g_Hl[(size_t)dst * D1C + c] = __float2bfloat16(v - __bfloat162float(hv));
    }
}

// ---------------- GAT layer-2 (all masks, compacted pairs) ----------------
__global__ void gat2_kernel(const float* __restrict__ xl, const float* __restrict__ xr,
                            const float* __restrict__ eproj,
                            const float* __restrict__ att, const float* __restrict__ bias,
                            float* __restrict__ out) {
    int p = blockIdx.x * 8 + (threadIdx.x >> 5);
    if (p >= g_pairofs[Aa]) return;
    int lane = threadIdx.x & 31;
    int packed = g_pair[p];
    int dst = packed & 0xFFFFF;
    int mi = packed >> 20;
    unsigned mbit = 1u << mi;
    const float* meanproj = g_meanproj2 + mi * D1C;

    float attreg[16], xrreg[16], acc[16];
    float m[4], r[4];
#pragma unroll
    for (int j = 0; j < 16; j++) {
        attreg[j] = att[(j >> 2) * 128 + lane + 32 * (j & 3)];
        xrreg[j] = xr[(size_t)dst * D1C + lane + 32 * j];
        acc[j] = 0.f;
    }
#pragma unroll
    for (int h = 0; h < 4; h++) { m[h] = -INFINITY; r[h] = 0.f; }

    int beg = g_offs[dst], end = g_offs[dst + 1];
    for (int k = beg; k <= end; k++) {
        int src;
        const float* eerow;
        if (k < end) {
            src = g_esrc[k];
            if (!(g_mask1[src] & mbit)) continue;
            eerow = eproj + (size_t)g_eattr[k] * D1C;
        } else {
            src = dst;
            eerow = meanproj;
        }
        const float* xlrow = xl + (size_t)src * D1C;
        float xlv[16];
        float sh0 = 0.f, sh1 = 0.f, sh2 = 0.f, sh3 = 0.f;
#pragma unroll
        for (int j = 0; j < 16; j++) {
            int c = lane + 32 * j;
            xlv[j] = xlrow[c];
            float z = xlv[j] + xrreg[j] + eerow[c];
            z = z > 0.f ? z : 0.2f * z;
            float pz = z * attreg[j];
            if (j < 4) sh0 += pz;
            else if (j < 8) sh1 += pz;
            else if (j < 12) sh2 += pz;
            else sh3 += pz;
        }
#pragma unroll
        for (int o = 16; o; o >>= 1) {
            sh0 += __shfl_xor_sync(0xffffffffu, sh0, o);
            sh1 += __shfl_xor_sync(0xffffffffu, sh1, o);
            sh2 += __shfl_xor_sync(0xffffffffu, sh2, o);
            sh3 += __shfl_xor_sync(0xffffffffu, sh3, o);
        }
        float sv[4] = {sh0, sh1, sh2, sh3};
        float scale[4], w[4];
#pragma unroll
        for (int h = 0; h < 4; h++) {
            float nm = fmaxf(m[h], sv[h]);
            scale[h] = __expf(m[h] - nm);
            w[h] = __expf(sv[h] - nm);
            r[h] = r[h] * scale[h] + w[h];
            m[h] = nm;
        }
#pragma unroll
        for (int j = 0; j < 16; j++)
            acc[j] = acc[j] * scale[j >> 2] + w[j >> 2] * xlv[j];
    }
#pragma unroll
    for (int j = 0; j < 16; j++) {
        int c = lane + 32 * j;
        out[(size_t)p * D1C + c] = acc[j] / (r[j >> 2] + 1e-16f) + bias[c];
    }
}

// ---------------- softmax aggregations (partials) ----------------
__device__ __forceinline__ void online1(float v, float& m, float& r, float& w) {
    if (v <= m) {
        float ev = __expf(v - m);
        r += ev;
        w += ev * v;
    } else {
        float sc = __expf(m - v);
        r = r * sc + 1.f;
        w = w * sc + v;
        m = v;
    }
}

__global__ void aggAF_kernel(const float* __restrict__ x) {
    int c = threadIdx.x, b = blockIdx.x;
    const int chunk = (Nn + NBF - 1) / NBF;
    int n0 = b * chunk, n1 = min(n0 + chunk, Nn);
    float m = -INFINITY, r = 0.f, w = 0.f;
    for (int n = n0; n < n1; n++)
        online1(x[(size_t)n * D1C + c], m, r, w);
    g_partF[(b * 3 + 0) * D1C + c] = m;
    g_partF[(b * 3 + 1) * D1C + c] = r;
    g_partF[(b * 3 + 2) * D1C + c] = w;
}

__global__ void aggP_kernel(const float* __restrict__ x) {
    int c = threadIdx.x, b = blockIdx.x, i = blockIdx.y;
    int beg = g_pairofs[i], end = g_pairofs[i + 1];
    int cnt = end - beg;
    int chunk = (cnt + NBM - 1) / NBM;
    int r0 = beg + b * chunk, r1 = min(r0 + chunk, end);
    float m = -INFINITY, r = 0.f, w = 0.f;
    for (int p = r0; p < r1; p++)
        online1(x[(size_t)p * D1C + c], m, r, w);
    int idx = i * NBM + b;
    g_partM[(idx * 3 + 0) * D1C + c] = m;
    g_partM[(idx * 3 + 1) * D1C + c] = r;
    g_partM[(idx * 3 + 2) * D1C + c] = w;
}

// ---------------- HGT head (fused final aggregations) ----------------
__device__ __forceinline__ float gelu_exact(float x) {
    return 0.5f * x * (1.f + erff(x * 0.70710678118654752f));
}

__global__ void head_kernel(const float* __restrict__ kqv_f, const float* __restrict__ kqvb_f,
                            const float* __restrict__ kqv_r, const float* __restrict__ kqvb_r,
                            const float* __restrict__ a_rel, const float* __restrict__ m_rel,
                            const float* __restrict__ p_rel,
                            const float* __restrict__ aW_f, const float* __restrict__ ab_f,
                            const float* __restrict__ aW_r, const float* __restrict__ ab_r,
                            const float* __restrict__ Wfr, const float* __restrict__ bfr,
                            const float* __restrict__ Wro, const float* __restrict__ bro,
                            float* __restrict__ out) {
    __shared__ float sF[512];
    __shared__ float BIG[4096];
    __shared__ float kf[64], vf[64];
    __shared__ float kr[512], qr[512], vr[512];
    __shared__ float kfa[64], kra[512];
    __shared__ float vfm0[64], vfm1[64], vrm2[512];
    __shared__ float aggr[512];
    __shared__ float outf[64], outr[512];
    __shared__ float red[32];
    __shared__ float scal[32];
    int t = threadIdx.x;

    {
        int c = t;
        float gm = -INFINITY;
        for (int b = 0; b < NBF; b++) {
            float rr = g_partF[(b * 3 + 1) * D1C + c];
            if (rr > 0.f) gm = fmaxf(gm, g_partF[(b * 3 + 0) * D1C + c]);
        }
        float R = 0.f, W = 0.f;
        for (int b = 0; b < NBF; b++) {
            float rr = g_partF[(b * 3 + 1) * D1C + c];
            if (rr > 0.f) {
                float sc = __expf(g_partF[(b * 3 + 0) * D1C + c] - gm);
                R += rr * sc;
                W += g_partF[(b * 3 + 2) * D1C + c] * sc;
            }
        }
        sF[c] = W / R;
    }
    for (int idx = t; idx < Aa * D1C; idx += 512) {
        int i = idx / D1C, c = idx % D1C;
        float gm = -INFINITY;
        for (int b = 0; b < NBM; b++) {
            int pi = i * NBM + b;
            float rr = g_partM[(pi * 3 + 1) * D1C + c];
            if (rr > 0.f) gm = fmaxf(gm, g_partM[(pi * 3 + 0) * D1C + c]);
        }
        float R = 0.f, W = 0.f;
        for (int b = 0; b < NBM; b++) {
            int pi = i * NBM + b;
            float rr = g_partM[(pi * 3 + 1) * D1C + c];
            if (rr > 0.f) {
                float sc = __expf(g_partM[(pi * 3 + 0) * D1C + c] - gm);
                R += rr * sc;
                W += g_partM[(pi * 3 + 2) * D1C + c] * sc;
            }
        }
        BIG[idx] = W / R;
    }
    __syncthreads();

    if (t < 128) {
        int o = t & 63, sel = t >> 6;
        const float* Wm = kqv_f + (sel ? 2 : 0) * 512 * 64;
        float s = kqvb_f[(sel ? 2 : 0) * 64 + o];
        for (int c = 0; c < 512; c++) s += sF[c] * Wm[c * 64 + o];
        if (sel) vf[o] = s; else kf[o] = s;
    }
    for (int idx = t; idx < 1536; idx += 512) {
        int a = idx / 192, rem = idx % 192, rsel = rem >> 6, o = rem & 63;
        const float* Wm = kqv_r + rsel * 512 * 64;
        float s = kqvb_r[rsel * 64 + o];
        const float* rx = BIG + a * 512;
        for (int c = 0; c < 512; c++) s += rx[c] * Wm[c * 64 + o];
        (rsel == 0 ? kr : rsel == 1 ? qr : vr)[a * 64 + o] = s;
    }
    __syncthreads();

    for (int o = t; o < 64; o += 512) {
        float s1 = 0.f, s2 = 0.f, s3 = 0.f;
        for (int c = 0; c < 64; c++) {
            s1 += kf[c] * a_rel[1 * 4096 + c * 64 + o];
            s2 += vf[c] * m_rel[0 * 4096 + c * 64 + o];
            s3 += vf[c] * m_rel[1 * 4096 + c * 64 + o];
        }
        kfa[o] = s1; vfm0[o] = s2; vfm1[o] = s3;
    }
    for (int idx = t; idx < 512; idx += 512) {
        int a = idx >> 6, o = idx & 63;
        float s1 = 0.f, s2 = 0.f;
        for (int c = 0; c < 64; c++) {
            s1 += kr[a * 64 + c] * a_rel[2 * 4096 + c * 64 + o];
            s2 += vr[a * 64 + c] * m_rel[2 * 4096 + c * 64 + o];
        }
        kra[idx] = s1; vrm2[idx] = s2;
    }
    __syncthreads();

    if (t < 8) {
        float sq = 0.125f;
        float sfr = 0.f, srr = 0.f;
        for (int o = 0; o < 64; o++) {
            sfr += qr[t * 64 + o] * kfa[o];
            srr += qr[t * 64 + o] * kra[t * 64 + o];
        }
        sfr *= sq * p_rel[1];
        srr *= sq * p_rel[2];
        float mx = fmaxf(sfr, srr);
        float e0 = __expf(sfr - mx), e1 = __expf(srr - mx);
        float den = e0 + e1;
        scal[2 * t] = e0 / den;
        scal[2 * t + 1] = e1 / den;
    }
    __syncthreads();

    if (t < 64) vfm0[t] = gelu_exact(vfm0[t]);
    {
        int a = t >> 6, o = t & 63;
        float v = scal[2 * a] * vfm1[o] + scal[2 * a + 1] * vrm2[t];
        aggr[t] = gelu_exact(v);
    }
    __syncthreads();

    if (t < 64) {
        float s = ab_f[t];
        for (int o = 0; o < 64; o++) s += vfm0[o] * aW_f[o * 64 + t];
        outf[t] = s;
    }
    {
        int a = t >> 6, o2 = t & 63;
        float s = ab_r[o2];
        for (int o = 0; o < 64; o++) s += aggr[a * 64 + o] * aW_r[o * 64 + o2];
        outr[t] = s;
    }
    __syncthreads();

    float* fl = BIG;
    float* rl = BIG + 2048;
    for (int f = t; f < NFC; f += 512) {
        float s = bfr[f];
        for (int o = 0; o < 64; o++) s += outf[o] * Wfr[o * NFC + f];
        fl[f] = s;
    }
    {
        int a = t >> 6, rr = t & 63;
        float s = bro[rr];
        for (int o = 0; o < 64; o++) s += outr[a * 64 + o] * Wro[o * NRC + rr];
        rl[t] = s;
    }
    __syncthreads();

    float lm = -INFINITY;
    for (int f = t; f < NFC; f += 512) lm = fmaxf(lm, fl[f]);
#pragma unroll
    for (int o = 16; o; o >>= 1) lm = fmaxf(lm, __shfl_xor_sync(0xffffffffu, lm, o));
    if ((t & 31) == 0) red[t >> 5] = lm;
    __syncthreads();
    if (t < 16) {
        float x = red[t];
#pragma unroll
        for (int o = 8; o; o >>= 1) x = fmaxf(x, __shfl_xor_sync(0xffffu, x, o));
        if (t == 0) red[0] = x;
    }
    __syncthreads();
    float gmax = red[0];
    __syncthreads();
    float ls = 0.f;
    for (int f = t; f < NFC; f += 512) ls += __expf(fl[f] - gmax);
#pragma unroll
    for (int o = 16; o; o >>= 1) ls += __shfl_xor_sync(0xffffffffu, ls, o);
    if ((t & 31) == 0) red[t >> 5] = ls;
    __syncthreads();
    if (t < 16) {
        float x = red[t];
#pragma unroll
        for (int o = 8; o; o >>= 1) x += __shfl_xor_sync(0xffffu, x, o);
        if (t == 0) red[0] = x;
    }
    __syncthreads();
    float lse = gmax + logf(red[0]);
    for (int f = t; f < NFC; f += 512) out[f] = fl[f] - lse;

    if (t < 8) {
        float mx = -INFINITY;
        for (int i = 0; i < 64; i++) mx = fmaxf(mx, rl[t * 64 + i]);
        float s = 0.f;
        for (int i = 0; i < 64; i++) s += __expf(rl[t * 64 + i] - mx);
        scal[t] = mx + logf(s);
    }
    __syncthreads();
    {
        int a = t >> 6;
        out[NFC + t] = rl[t] - scal[a];
    }
}

// ---------------- launch: serial main + one side stream ----------------
extern "C" void kernel_launch(void* const* d_in, const int* in_sizes, int n_in,
                              void* d_out, int out_size) {
    const int* node_pred = (const int*)d_in[0];
    const int* ei = (const int*)d_in[1];
    const int* eattr = (const int*)d_in[2];
    const int* args = (const int*)d_in[3];
    const float* pred_emb = (const float*)d_in[4];
    const float* Wl1 = (const float*)d_in[5];
    const float* Wr1 = (const float*)d_in[6];
    const float* We1 = (const float*)d_in[7];
    const float* att1 = (const float*)d_in[8];
    const float* b1 = (const float*)d_in[9];
    const float* Wl2 = (const float*)d_in[10];
    const float* Wr2 = (const float*)d_in[11];
    const float* We2 = (const float*)d_in[12];
    const float* att2 = (const float*)d_in[13];
    const float* b2 = (const float*)d_in[14];
    const float* kqv_f = (const float*)d_in[15];
    const float* kqvb_f = (const float*)d_in[16];
    const float* kqv_r = (const float*)d_in[17];
    const float* kqvb_r = (const float*)d_in[18];
    const float* a_rel = (const float*)d_in[19];
    const float* m_rel = (const float*)d_in[20];
    const float* p_rel = (const float*)d_in[21];
    const float* aW_f = (const float*)d_in[22];
    const float* ab_f = (const float*)d_in[23];
    const float* aW_r = (const float*)d_in[24];
    const float* ab_r = (const float*)d_in[25];
    const float* Wfr = (const float*)d_in[26];
    const float* bfr = (const float*)d_in[27];
    const float* Wro = (const float*)d_in[28];
    const float* bro = (const float*)d_in[29];
    float* out = (float*)d_out;

    float *p_xl1, *p_xr1, *p_xl2, *p_xr2, *p_h, *p_hbuf2;
    float *p_ep1, *p_ep2, *p_mp1;
    __nv_bfloat16 *p_ah1, *p_al1, *p_hh, *p_hl, *p_bh1, *p_bl1, *p_bh2, *p_bl2;
    cudaGetSymbolAddress((void**)&p_xl1, g_xl1);
    cudaGetSymbolAddress((void**)&p_xr1, g_xr1);
    cudaGetSymbolAddress((void**)&p_xl2, g_xl2);
    cudaGetSymbolAddress((void**)&p_xr2, g_xr2);
    cudaGetSymbolAddress((void**)&p_h, g_h);
    cudaGetSymbolAddress((void**)&p_hbuf2, g_hbuf2);
    cudaGetSymbolAddress((void**)&p_ep1, g_eproj1);
    cudaGetSymbolAddress((void**)&p_ep2, g_eproj2);
    cudaGetSymbolAddress((void**)&p_mp1, g_meanproj1);
    cudaGetSymbolAddress((void**)&p_ah1, g_Ah1);
    cudaGetSymbolAddress((void**)&p_al1, g_Al1);
    cudaGetSymbolAddress((void**)&p_hh, g_Hh);
    cudaGetSymbolAddress((void**)&p_hl, g_Hl);
    cudaGetSymbolAddress((void**)&p_bh1, g_Bh1);
    cudaGetSymbolAddress((void**)&p_bl1, g_Bl1);
    cudaGetSymbolAddress((void**)&p_bh2, g_Bh2);
    cudaGetSymbolAddress((void**)&p_bl2, g_Bl2);

    cudaFuncSetAttribute(mma_gemm_kernel, cudaFuncAttributeMaxDynamicSharedMemorySize, GDYN);

    static cudaStream_t s2 = nullptr;
    static cudaEvent_t eZ = nullptr, eE = nullptr, eS2 = nullptr;
    if (s2 == nullptr) {
        cudaStreamCreateWithFlags(&s2, cudaStreamNonBlocking);
        cudaEventCreateWithFlags(&eZ, cudaEventDisableTiming);
        cudaEventCreateWithFlags(&eE, cudaEventDisableTiming);
        cudaEventCreateWithFlags(&eS2, cudaEventDisableTiming);
    }

    // main prefix
    zeroK_kernel<<<20, 512>>>();
    cudaEventRecord(eZ, 0);
    wsplitT_kernel<<<dim3(4, 16), 256>>>(Wl1, p_bh1, p_bl1, EMBC, 0);
    wsplitT_kernel<<<dim3(4, 16), 256>>>(Wr1, p_bh1, p_bl1, EMBC, 512);
    gsplit1_kernel<<<1250, 256>>>(pred_emb, node_pred);
    eproj_kernel<<<128, 512>>>(pred_emb, We1, We2);
    cudaEventRecord(eE, 0);

    // side: BFS -> histM -> meanprojM -> pairscan (gates only gat2)
    cudaStreamWaitEvent(s2, eZ, 0);
    seedK_kernel<<<1, 32, 0, s2>>>(args);
    copy_mask_kernel<<<20, 512, 0, s2>>>(0);
    hop_kernel<<<625, 256, 0, s2>>>(ei, 0);
    copy_mask_kernel<<<20, 512, 0, s2>>>(1);
    hop_kernel<<<625, 256, 0, s2>>>(ei, 1);
    copy_mask_kernel<<<20, 512, 0, s2>>>(0);
    hop_kernel<<<625, 256, 0, s2>>>(ei, 0);
    histM_kernel<<<128, 256, 0, s2>>>(ei, eattr);
    cudaStreamWaitEvent(s2, eE, 0);
    meanprojM_kernel<<<Aa, 512, 0, s2>>>();
    pairscan_kernel<<<1, 1024, 0, s2>>>();
    cudaEventRecord(eS2, s2);

    // main: CSR + frame meanproj
    degK_kernel<<<625, 256>>>(ei);
    scan_kernel<<<1, 1024>>>();
    fill_kernel<<<625, 256>>>(ei, eattr);
    histF_kernel<<<128, 256>>>(eattr);
    meanprojF_kernel<<<1, 512>>>();

    // layer-1 GEMM (pipelined, bf16 A) -> gat1 -> frame partials
    mma_gemm_kernel<<<dim3(79, 8), 256, GDYN>>>(p_ah1, p_al1, p_bh1, p_bl1, p_xl1, p_xr1, EMBC);
    gat1_kernel<<<1250, 256>>>(p_xl1, p_xr1, p_ep1, p_mp1, att1, b1, p_h);
    aggAF_kernel<<<NBF, 512>>>(p_h);

    // layer-2 weight split + GEMM
    wsplitT_kernel<<<dim3(16, 16), 256>>>(Wl2, p_bh2, p_bl2, D1C, 0);
    wsplitT_kernel<<<dim3(16, 16), 256>>>(Wr2, p_bh2, p_bl2, D1C, 512);
    mma_gemm_kernel<<<dim3(79, 8), 256, GDYN>>>(p_hh, p_hl, p_bh2, p_bl2, p_xl2, p_xr2, D1C);

    // masked GAT + role partials + head
    cudaStreamWaitEvent(0, eS2, 0);
    gat2_kernel<<<Nn, 256>>>(p_xl2, p_xr2, p_ep2, att2, b2, p_hbuf2);
    aggP_kernel<<<dim3(NBM, Aa), 512>>>(p_hbuf2);
    head_kernel<<<1, 512>>>(kqv_f, kqvb_f, kqv_r, kqvb_r, a_rel, m_rel, p_rel,
                            aW_f, ab_f, aW_r, ab_r, Wfr, bfr, Wro, bro, out);
}